// round 7
// baseline (speedup 1.0000x reference)
#include <cuda_runtime.h>
#include <cstdint>

#define MDIM 16384
#define NDIM 4096
#define KDIM 4096
#define BM 128
#define BN 128
#define BK 64
#define NKT (KDIM / BK)             // 64
#define STAGE_BYTES 32768           // 4 planes x 128 rows x 64 B
#define SMEM_BYTES (3 * STAGE_BYTES)
#define NTHR 256

// int8 planes, column-permuted per 64-col block:
//   new[t*16 + seg*4 + j] = old[seg*16 + t*4 + j]   (t,seg: 0..3, j: 0..3)
// so mma thread t reads its 16 fragment bytes (k-group 0+1) as ONE LDS.128.
__device__ int8_t g_q1x[(size_t)MDIM * KDIM];
__device__ int8_t g_q2x[(size_t)MDIM * KDIM];
__device__ int8_t g_q1w[(size_t)NDIM * KDIM];
__device__ int8_t g_q2w[(size_t)NDIM * KDIM];
__device__ float  g_sx[MDIM];
__device__ float  g_sw[NDIM];

// ---------------- helpers ----------------
__device__ __forceinline__ uint32_t smem_u32(const void* p) {
    uint32_t a;
    asm("{ .reg .u64 t; cvta.to.shared.u64 t, %1; cvt.u32.u64 %0, t; }" : "=r"(a) : "l"(p));
    return a;
}
__device__ __forceinline__ void cp_async16(uint32_t saddr, const void* gptr) {
    asm volatile("cp.async.cg.shared.global [%0], [%1], 16;"
                 :: "r"(saddr), "l"(__cvta_generic_to_global(gptr)) : "memory");
}
#define CP_COMMIT() asm volatile("cp.async.commit_group;" ::: "memory")
#define CP_WAIT1()  asm volatile("cp.async.wait_group 1;" ::: "memory")
#define CP_WAIT0()  asm volatile("cp.async.wait_group 0;" ::: "memory")

__device__ __forceinline__ uint4 lds128(uint32_t addr) {
    uint4 v;
    asm volatile("ld.shared.v4.b32 {%0,%1,%2,%3}, [%4];"
                 : "=r"(v.x), "=r"(v.y), "=r"(v.z), "=r"(v.w) : "r"(addr));
    return v;
}
__device__ __forceinline__ void imma(int c[4], uint32_t a0, uint32_t a1,
                                     uint32_t a2, uint32_t a3,
                                     uint32_t b0, uint32_t b1) {
    asm volatile(
        "mma.sync.aligned.m16n8k32.row.col.s32.s8.s8.s32 "
        "{%0,%1,%2,%3}, {%4,%5,%6,%7}, {%8,%9}, {%0,%1,%2,%3};"
        : "+r"(c[0]), "+r"(c[1]), "+r"(c[2]), "+r"(c[3])
        : "r"(a0), "r"(a1), "r"(a2), "r"(a3), "r"(b0), "r"(b1));
}

// quantize 4 consecutive cols (c0 % 4 == 0) into both planes, write packed u32s
__device__ __forceinline__ void quant_store4(int8_t* p1, int8_t* p2, size_t rowbase,
                                             int c0, float4 v, float s1, float inv1,
                                             float inv2) {
    float q1f[4], rf[4];
    int q1[4], q2[4];
    float vv[4] = {v.x, v.y, v.z, v.w};
#pragma unroll
    for (int j = 0; j < 4; j++) {
        q1f[j] = rintf(vv[j] * inv1);
        q1f[j] = fminf(127.f, fmaxf(-127.f, q1f[j]));
        q1[j] = (int)q1f[j];
        rf[j] = fmaf(-q1f[j], s1, vv[j]);
        int q = (int)rintf(rf[j] * inv2);
        q2[j] = max(-127, min(127, q));
    }
    uint32_t p1w = (q1[0] & 0xFF) | ((q1[1] & 0xFF) << 8) |
                   ((q1[2] & 0xFF) << 16) | ((uint32_t)(q1[3] & 0xFF) << 24);
    uint32_t p2w = (q2[0] & 0xFF) | ((q2[1] & 0xFF) << 8) |
                   ((q2[2] & 0xFF) << 16) | ((uint32_t)(q2[3] & 0xFF) << 24);
    int pos = (c0 & ~63) + (((c0 >> 2) & 3) << 4) + (((c0 >> 4) & 3) << 2);
    *(uint32_t*)(p1 + rowbase + pos) = p1w;
    *(uint32_t*)(p2 + rowbase + pos) = p2w;
}

// ---------------- prep x: per-row max, 2-plane quantize ----------------
__global__ void prep_x_kernel(const float* __restrict__ x) {
    __shared__ float red[256];
    int m = blockIdx.x, tid = threadIdx.x;
    const float4* row = (const float4*)(x + (size_t)m * KDIM);
    float4 vv[4];
    float mx = 0.f;
#pragma unroll
    for (int i = 0; i < 4; i++) {
        vv[i] = row[tid + 256 * i];
        mx = fmaxf(mx, fmaxf(fmaxf(fabsf(vv[i].x), fabsf(vv[i].y)),
                             fmaxf(fabsf(vv[i].z), fabsf(vv[i].w))));
    }
    red[tid] = mx;
    __syncthreads();
    for (int off = 128; off; off >>= 1) {
        if (tid < off) red[tid] = fmaxf(red[tid], red[tid + off]);
        __syncthreads();
    }
    float m0 = red[0];
    float s1 = (m0 > 0.f) ? m0 / 127.f : 1.f;
    float inv1 = (m0 > 0.f) ? 127.f / m0 : 0.f;
    float inv2 = inv1 * 254.f;
    if (tid == 0) g_sx[m] = s1;
    size_t rb = (size_t)m * KDIM;
#pragma unroll
    for (int i = 0; i < 4; i++)
        quant_store4(g_q1x, g_q2x, rb, 4 * (tid + 256 * i), vv[i], s1, inv1, inv2);
}

// ---------------- prep w: fold LoRA, per-row max, quantize ----------------
__global__ void prep_w_kernel(const float* __restrict__ w, const float* __restrict__ lA,
                              const float* __restrict__ lB) {
    __shared__ float red[256];
    int o = blockIdx.x, tid = threadIdx.x;
    float bv[16];
#pragma unroll
    for (int r = 0; r < 16; r++) bv[r] = lB[o * 16 + r] * 2.0f;
    const float4* wr = (const float4*)(w + (size_t)o * KDIM);
    float4 vv[4];
    float mx = 0.f;
#pragma unroll
    for (int i = 0; i < 4; i++) {
        int j = tid + 256 * i;
        float4 acc = wr[j];
#pragma unroll
        for (int r = 0; r < 16; r++) {
            float4 a = ((const float4*)(lA + (size_t)r * KDIM))[j];
            acc.x += bv[r] * a.x; acc.y += bv[r] * a.y;
            acc.z += bv[r] * a.z; acc.w += bv[r] * a.w;
        }
        vv[i] = acc;
        mx = fmaxf(mx, fmaxf(fmaxf(fabsf(acc.x), fabsf(acc.y)),
                             fmaxf(fabsf(acc.z), fabsf(acc.w))));
    }
    red[tid] = mx;
    __syncthreads();
    for (int off = 128; off; off >>= 1) {
        if (tid < off) red[tid] = fmaxf(red[tid], red[tid + off]);
        __syncthreads();
    }
    float m0 = red[0];
    float s1 = (m0 > 0.f) ? m0 / 127.f : 1.f;
    float inv1 = (m0 > 0.f) ? 127.f / m0 : 0.f;
    float inv2 = inv1 * 254.f;
    if (tid == 0) g_sw[o] = s1;
    size_t rb = (size_t)o * KDIM;
#pragma unroll
    for (int i = 0; i < 4; i++)
        quant_store4(g_q1w, g_q2w, rb, 4 * (tid + 256 * i), vv[i], s1, inv1, inv2);
}

// one pass: 4ma x 4na x 2 k-groups of IMMA
#define PASS(ACC, U, V, W)                                                        \
    do {                                                                          \
        _Pragma("unroll")                                                         \
        for (int ma = 0; ma < 4; ma++)                                            \
            _Pragma("unroll")                                                     \
            for (int na = 0; na < 4; na++)                                        \
                imma(ACC[ma][na], (U)[ma].x, (V)[ma].x, (U)[ma].y, (V)[ma].y,     \
                     (W)[na].x, (W)[na].y);                                       \
        _Pragma("unroll")                                                         \
        for (int ma = 0; ma < 4; ma++)                                            \
            _Pragma("unroll")                                                     \
            for (int na = 0; na < 4; na++)                                        \
                imma(ACC[ma][na], (U)[ma].z, (V)[ma].z, (U)[ma].w, (V)[ma].w,     \
                     (W)[na].z, (W)[na].w);                                       \
    } while (0)

// ---------------- main GEMM: int8 3-pass, BM=BN=128, BK=64 ----------------
__global__ __launch_bounds__(NTHR, 1)
void lora_gemm_kernel(const float* __restrict__ bias, float* __restrict__ out) {
    extern __shared__ char smem[];
    const int tid = threadIdx.x;
    const int wid = tid >> 5, lane = tid & 31;
    const int wm = wid >> 2, wn = wid & 3;        // 2 x 4 warps, warp tile 64x32
    const int m0 = blockIdx.x * BM, n0 = blockIdx.y * BN;
    const uint32_t sbase = smem_u32(smem);

    auto issue = [&](int s, int kt) {
        uint32_t st = sbase + s * STAGE_BYTES;
#pragma unroll
        for (int i = 0; i < 8; i++) {
            int c = tid + i * 256;
            int plane = c >> 9, r = (c >> 2) & 127, q = c & 3;
            const int8_t* g;
            if (plane == 0)      g = g_q1x + (size_t)(m0 + r) * KDIM;
            else if (plane == 1) g = g_q2x + (size_t)(m0 + r) * KDIM;
            else if (plane == 2) g = g_q1w + (size_t)(n0 + r) * KDIM;
            else                 g = g_q2w + (size_t)(n0 + r) * KDIM;
            cp_async16(st + c * 16, g + kt * BK + q * 16);
        }
    };

    int acc1[4][4][4], accX[4][4][4];
#pragma unroll
    for (int ma = 0; ma < 4; ma++)
#pragma unroll
        for (int na = 0; na < 4; na++)
#pragma unroll
            for (int j = 0; j < 4; j++) { acc1[ma][na][j] = 0; accX[ma][na][j] = 0; }

    issue(0, 0); CP_COMMIT();
    issue(1, 1); CP_COMMIT();

    const int g = lane >> 2, t = lane & 3;
    const uint32_t aoff = (wm * 64 + g) * 64 + t * 16;
    const uint32_t boff = (wn * 32 + g) * 64 + t * 16;

    for (int kt = 0; kt < NKT; ++kt) {
        int s = kt - (kt / 3) * 3;
        if (kt + 2 < NKT) { CP_WAIT1(); } else { CP_WAIT0(); }
        __syncthreads();
        if (kt + 2 < NKT) {
            int s2 = (kt + 2) - ((kt + 2) / 3) * 3;
            issue(s2, kt + 2);
            CP_COMMIT();
        }

        uint32_t base = sbase + s * STAGE_BYTES;
        uint32_t q1x = base, q2x = base + 8192, q1w = base + 16384, q2w = base + 24576;

        uint4 u1[4], v1[4], w1[4];
#pragma unroll
        for (int ma = 0; ma < 4; ma++) {
            u1[ma] = lds128(q1x + aoff + ma * 1024);
            v1[ma] = lds128(q1x + aoff + ma * 1024 + 512);
        }
#pragma unroll
        for (int na = 0; na < 4; na++)
            w1[na] = lds128(q1w + boff + na * 512);

        PASS(acc1, u1, v1, w1);                 // P11

        uint4 w2[4];
#pragma unroll
        for (int na = 0; na < 4; na++)
            w2[na] = lds128(q2w + boff + na * 512);

        PASS(accX, u1, v1, w2);                 // P12 (q1x * q2w)

        uint4 u2[4], v2[4];
#pragma unroll
        for (int ma = 0; ma < 4; ma++) {
            u2[ma] = lds128(q2x + aoff + ma * 1024);
            v2[ma] = lds128(q2x + aoff + ma * 1024 + 512);
        }

        PASS(accX, u2, v2, w1);                 // P21 (q2x * q1w)
    }

    // epilogue: out = sx*sw*(P11 + (P12+P21)/254) + bias
    const float inv254 = 1.0f / 254.0f;
#pragma unroll
    for (int ma = 0; ma < 4; ma++) {
        int mA = m0 + wm * 64 + ma * 16 + g;
        float sxa = g_sx[mA], sxb = g_sx[mA + 8];
#pragma unroll
        for (int na = 0; na < 4; na++) {
            int n = n0 + wn * 32 + na * 8 + 2 * t;
            float sw0 = g_sw[n], sw1 = g_sw[n + 1];
            float b0 = bias[n], b1 = bias[n + 1];
            float f0 = (float)acc1[ma][na][0] + (float)accX[ma][na][0] * inv254;
            float f1 = (float)acc1[ma][na][1] + (float)accX[ma][na][1] * inv254;
            float f2 = (float)acc1[ma][na][2] + (float)accX[ma][na][2] * inv254;
            float f3 = (float)acc1[ma][na][3] + (float)accX[ma][na][3] * inv254;
            float2 r0 = make_float2(sxa * sw0 * f0 + b0, sxa * sw1 * f1 + b1);
            float2 r1 = make_float2(sxb * sw0 * f2 + b0, sxb * sw1 * f3 + b1);
            *(float2*)(out + (size_t)mA * NDIM + n) = r0;
            *(float2*)(out + (size_t)(mA + 8) * NDIM + n) = r1;
        }
    }
}

// ---------------- launch ----------------
extern "C" void kernel_launch(void* const* d_in, const int* in_sizes, int n_in,
                              void* d_out, int out_size) {
    const float* x      = (const float*)d_in[0];
    const float* weight = (const float*)d_in[1];
    const float* bias   = (const float*)d_in[2];
    const float* lora_A = (const float*)d_in[3];
    const float* lora_B = (const float*)d_in[4];
    float* out = (float*)d_out;

    cudaFuncSetAttribute(lora_gemm_kernel, cudaFuncAttributeMaxDynamicSharedMemorySize,
                         SMEM_BYTES);

    prep_x_kernel<<<MDIM, 256>>>(x);
    prep_w_kernel<<<NDIM, 256>>>(weight, lora_A, lora_B);
    dim3 grid(MDIM / BM, NDIM / BN);
    lora_gemm_kernel<<<grid, NTHR, SMEM_BYTES>>>(bias, out);
}

// round 8
// speedup vs baseline: 5.6899x; 5.6899x over previous
#include <cuda_runtime.h>
#include <cuda_fp16.h>
#include <cstdint>

#define MDIM 16384
#define NDIM 4096
#define KDIM 4096
#define BM 128
#define BN 256
#define BK 32
#define NKT (KDIM / BK)             // 128
#define A_BYTES (BM * 64)           // 8192  (64 B per row per k-tile)
#define B_BYTES (BN * 64)           // 16384
#define STAGE_BYTES (A_BYTES + B_BYTES)   // 24576
#define SMEM_BYTES (3 * STAGE_BYTES)      // 73728
#define NTHR 256

// fp16 operands, word-transposed within each 64-byte (32-col) block:
//   new_word[(o&3)*4 + (o>>2)] = old_word[o]   (16 4-byte words per block)
// so mma-thread t's four needed words {t, t+4, t+8, t+12} (k-pairs for both
// k16 groups) sit contiguous at new words 4t..4t+3 -> ONE LDS.128 per row.
__device__ __half g_xh[(size_t)MDIM * KDIM];
__device__ __half g_wh[(size_t)NDIM * KDIM];

// ---------------- helpers ----------------
__device__ __forceinline__ uint32_t smem_u32(const void* p) {
    uint32_t a;
    asm("{ .reg .u64 t; cvta.to.shared.u64 t, %1; cvt.u32.u64 %0, t; }" : "=r"(a) : "l"(p));
    return a;
}
__device__ __forceinline__ void cp_async16(uint32_t saddr, const void* gptr) {
    asm volatile("cp.async.cg.shared.global [%0], [%1], 16;"
                 :: "r"(saddr), "l"(__cvta_generic_to_global(gptr)) : "memory");
}
#define CP_COMMIT() asm volatile("cp.async.commit_group;" ::: "memory")
#define CP_WAIT1()  asm volatile("cp.async.wait_group 1;" ::: "memory")
#define CP_WAIT0()  asm volatile("cp.async.wait_group 0;" ::: "memory")

__device__ __forceinline__ uint4 lds128(uint32_t addr) {
    uint4 v;
    asm volatile("ld.shared.v4.b32 {%0,%1,%2,%3}, [%4];"
                 : "=r"(v.x), "=r"(v.y), "=r"(v.z), "=r"(v.w) : "r"(addr));
    return v;
}
__device__ __forceinline__ void hmma(float c[4], uint32_t a0, uint32_t a1,
                                     uint32_t a2, uint32_t a3,
                                     uint32_t b0, uint32_t b1) {
    asm volatile(
        "mma.sync.aligned.m16n8k16.row.col.f32.f16.f16.f32 "
        "{%0,%1,%2,%3}, {%4,%5,%6,%7}, {%8,%9}, {%0,%1,%2,%3};"
        : "+f"(c[0]), "+f"(c[1]), "+f"(c[2]), "+f"(c[3])
        : "r"(a0), "r"(a1), "r"(a2), "r"(a3), "r"(b0), "r"(b1));
}
// transposed word position within a 64B block
__device__ __forceinline__ int tpos(int o) { return ((o & 3) << 2) | (o >> 2); }

// convert 4 consecutive fp32 cols (col0 % 4 == 0) and store word-transposed
__device__ __forceinline__ void cvt_store4(__half* dst, size_t row, int col0, float4 v) {
    __half2 h0 = __floats2half2_rn(v.x, v.y);
    __half2 h1 = __floats2half2_rn(v.z, v.w);
    char* bb = (char*)dst + row * (KDIM * 2) + (col0 >> 5) * 64;
    int W = (col0 >> 1) & 15;
    *(uint32_t*)(bb + tpos(W) * 4)     = *(uint32_t*)&h0;
    *(uint32_t*)(bb + tpos(W + 1) * 4) = *(uint32_t*)&h1;
}

// ---------------- prep x: fp32 -> fp16 permuted ----------------
__global__ void prep_x_kernel(const float* __restrict__ x) {
    size_t n4 = (size_t)MDIM * KDIM / 4;
    size_t stride = (size_t)gridDim.x * blockDim.x;
    const float4* in = (const float4*)x;
    for (size_t i = blockIdx.x * (size_t)blockDim.x + threadIdx.x; i < n4; i += stride) {
        float4 v = in[i];
        cvt_store4(g_xh, i >> 10, ((int)i & 1023) * 4, v);
    }
}

// ---------------- prep w: fold LoRA, fp32 -> fp16 permuted ----------------
__global__ void prep_w_kernel(const float* __restrict__ w, const float* __restrict__ lA,
                              const float* __restrict__ lB) {
    int o = blockIdx.x, tid = threadIdx.x;
    float bv[16];
#pragma unroll
    for (int r = 0; r < 16; r++) bv[r] = lB[o * 16 + r] * 2.0f;
    const float4* wr = (const float4*)(w + (size_t)o * KDIM);
#pragma unroll 4
    for (int i = 0; i < 4; i++) {
        int j = tid + 256 * i;
        float4 acc = wr[j];
#pragma unroll
        for (int r = 0; r < 16; r++) {
            float4 a = ((const float4*)(lA + (size_t)r * KDIM))[j];
            acc.x += bv[r] * a.x; acc.y += bv[r] * a.y;
            acc.z += bv[r] * a.z; acc.w += bv[r] * a.w;
        }
        cvt_store4(g_wh, o, j * 4, acc);
    }
}

// ---------------- main GEMM: fp16 m16n8k16, BM=128 BN=256 BK=32 ----------------
__global__ __launch_bounds__(NTHR, 1)
void lora_gemm_kernel(const float* __restrict__ bias, float* __restrict__ out) {
    extern __shared__ char smem[];
    const int tid = threadIdx.x;
    const int wid = tid >> 5, lane = tid & 31;
    const int wm = wid >> 2, wn = wid & 3;            // 2 x 4 warps, tile 64x64
    const int m0 = blockIdx.x * BM, n0 = blockIdx.y * BN;
    const uint32_t sbase = smem_u32(smem);

    auto issue = [&](int s, int kt) {
        uint32_t st = sbase + s * STAGE_BYTES;
#pragma unroll
        for (int i = 0; i < 2; i++) {                 // A: 512 chunks of 16B
            int c = tid + i * 256;
            int row = c >> 2, q = c & 3;
            cp_async16(st + c * 16,
                       (const char*)g_xh + (size_t)(m0 + row) * (KDIM * 2) + kt * 64 + q * 16);
        }
#pragma unroll
        for (int i = 0; i < 4; i++) {                 // B: 1024 chunks
            int c = tid + i * 256;
            int row = c >> 2, q = c & 3;
            cp_async16(st + A_BYTES + c * 16,
                       (const char*)g_wh + (size_t)(n0 + row) * (KDIM * 2) + kt * 64 + q * 16);
        }
    };

    float acc[4][8][4];
#pragma unroll
    for (int ma = 0; ma < 4; ma++)
#pragma unroll
        for (int na = 0; na < 8; na++)
#pragma unroll
            for (int j = 0; j < 4; j++) acc[ma][na][j] = 0.0f;

    issue(0, 0); CP_COMMIT();
    issue(1, 1); CP_COMMIT();

    const int g = lane >> 2, t = lane & 3;
    for (int kt = 0; kt < NKT; ++kt) {
        int s = kt - (kt / 3) * 3;
        if (kt + 2 < NKT) { CP_WAIT1(); } else { CP_WAIT0(); }
        __syncthreads();
        if (kt + 2 < NKT) {
            int s2 = (kt + 2) - ((kt + 2) / 3) * 3;
            issue(s2, kt + 2);
            CP_COMMIT();
        }

        uint32_t aB = sbase + s * STAGE_BYTES;
        uint32_t bB = aB + A_BYTES;
        uint32_t pa = aB + (wm * 64 + g) * 64 + t * 16;
        uint32_t pb = bB + (wn * 64 + g) * 64 + t * 16;

        uint4 u[4], v[4], w[8];
#pragma unroll
        for (int ma = 0; ma < 4; ma++) {
            u[ma] = lds128(pa + ma * (16 * 64));           // row g + 16ma
            v[ma] = lds128(pa + ma * (16 * 64) + 8 * 64);  // row g+8 + 16ma
        }
#pragma unroll
        for (int na = 0; na < 8; na++)
            w[na] = lds128(pb + na * (8 * 64));            // n-row g + 8na

        // k-group 0 (k 0..15)
#pragma unroll
        for (int ma = 0; ma < 4; ma++)
#pragma unroll
            for (int na = 0; na < 8; na++)
                hmma(acc[ma][na], u[ma].x, v[ma].x, u[ma].y, v[ma].y,
                     w[na].x, w[na].y);
        // k-group 1 (k 16..31)
#pragma unroll
        for (int ma = 0; ma < 4; ma++)
#pragma unroll
            for (int na = 0; na < 8; na++)
                hmma(acc[ma][na], u[ma].z, v[ma].z, u[ma].w, v[ma].w,
                     w[na].z, w[na].w);
    }

    // epilogue: fused bias + coalesced float2 stores
    const int r0 = m0 + wm * 64 + g;
    const int cbase = n0 + wn * 64 + t * 2;
    float2 bv[8];
#pragma unroll
    for (int na = 0; na < 8; na++)
        bv[na] = *(const float2*)(bias + cbase + na * 8);
#pragma unroll
    for (int ma = 0; ma < 4; ma++) {
        size_t row = (size_t)(r0 + ma * 16);
#pragma unroll
        for (int na = 0; na < 8; na++) {
            float2 v0 = make_float2(acc[ma][na][0] + bv[na].x, acc[ma][na][1] + bv[na].y);
            float2 v1 = make_float2(acc[ma][na][2] + bv[na].x, acc[ma][na][3] + bv[na].y);
            *(float2*)(out + row * NDIM + cbase + na * 8) = v0;
            *(float2*)(out + (row + 8) * NDIM + cbase + na * 8) = v1;
        }
    }
}

// ---------------- launch ----------------
extern "C" void kernel_launch(void* const* d_in, const int* in_sizes, int n_in,
                              void* d_out, int out_size) {
    const float* x      = (const float*)d_in[0];
    const float* weight = (const float*)d_in[1];
    const float* bias   = (const float*)d_in[2];
    const float* lora_A = (const float*)d_in[3];
    const float* lora_B = (const float*)d_in[4];
    float* out = (float*)d_out;

    cudaFuncSetAttribute(lora_gemm_kernel, cudaFuncAttributeMaxDynamicSharedMemorySize,
                         SMEM_BYTES);

    prep_x_kernel<<<8192, 256>>>(x);
    prep_w_kernel<<<NDIM, 256>>>(weight, lora_A, lora_B);
    dim3 grid(MDIM / BM, NDIM / BN);
    lora_gemm_kernel<<<grid, NTHR, SMEM_BYTES>>>(bias, out);
}

// round 9
// speedup vs baseline: 6.2867x; 1.1049x over previous
#include <cuda_runtime.h>
#include <cuda_fp16.h>
#include <cstdint>

#define MDIM 16384
#define NDIM 4096
#define KDIM 4096
#define BM 128
#define BN 256
#define BK 32
#define NKT (KDIM / BK)             // 128
#define A_BYTES (BM * 64)           // 8192  (64 B per row per k-tile)
#define B_BYTES (BN * 64)           // 16384
#define STAGE_BYTES (A_BYTES + B_BYTES)   // 24576
#define SMEM_BYTES (3 * STAGE_BYTES)      // 73728
#define NTHR 512

// fp16 operands, word-transposed within each 64-byte (32-col) block:
//   new_word[(o&3)*4 + (o>>2)] = old_word[o]   (16 4-byte words per block)
// so mma-thread t's four needed words {t, t+4, t+8, t+12} (k-pairs for both
// k16 groups) sit contiguous at new words 4t..4t+3 -> ONE LDS.128 per row.
__device__ __half g_xh[(size_t)MDIM * KDIM];
__device__ __half g_wh[(size_t)NDIM * KDIM];

// ---------------- helpers ----------------
__device__ __forceinline__ uint32_t smem_u32(const void* p) {
    uint32_t a;
    asm("{ .reg .u64 t; cvta.to.shared.u64 t, %1; cvt.u32.u64 %0, t; }" : "=r"(a) : "l"(p));
    return a;
}
__device__ __forceinline__ void cp_async16(uint32_t saddr, const void* gptr) {
    asm volatile("cp.async.cg.shared.global [%0], [%1], 16;"
                 :: "r"(saddr), "l"(__cvta_generic_to_global(gptr)) : "memory");
}
#define CP_COMMIT() asm volatile("cp.async.commit_group;" ::: "memory")
#define CP_WAIT1()  asm volatile("cp.async.wait_group 1;" ::: "memory")
#define CP_WAIT0()  asm volatile("cp.async.wait_group 0;" ::: "memory")

__device__ __forceinline__ uint4 lds128(uint32_t addr) {
    uint4 v;
    asm volatile("ld.shared.v4.b32 {%0,%1,%2,%3}, [%4];"
                 : "=r"(v.x), "=r"(v.y), "=r"(v.z), "=r"(v.w) : "r"(addr));
    return v;
}
__device__ __forceinline__ void hmma(float c[4], uint32_t a0, uint32_t a1,
                                     uint32_t a2, uint32_t a3,
                                     uint32_t b0, uint32_t b1) {
    asm volatile(
        "mma.sync.aligned.m16n8k16.row.col.f32.f16.f16.f32 "
        "{%0,%1,%2,%3}, {%4,%5,%6,%7}, {%8,%9}, {%0,%1,%2,%3};"
        : "+f"(c[0]), "+f"(c[1]), "+f"(c[2]), "+f"(c[3])
        : "r"(a0), "r"(a1), "r"(a2), "r"(a3), "r"(b0), "r"(b1));
}
// transposed word position within a 64B block
__device__ __forceinline__ int tpos(int o) { return ((o & 3) << 2) | (o >> 2); }

// convert 4 consecutive fp32 cols (col0 % 4 == 0) and store word-transposed
__device__ __forceinline__ void cvt_store4(__half* dst, size_t row, int col0, float4 v) {
    __half2 h0 = __floats2half2_rn(v.x, v.y);
    __half2 h1 = __floats2half2_rn(v.z, v.w);
    char* bb = (char*)dst + row * (KDIM * 2) + (col0 >> 5) * 64;
    int W = (col0 >> 1) & 15;
    *(uint32_t*)(bb + tpos(W) * 4)     = *(uint32_t*)&h0;
    *(uint32_t*)(bb + tpos(W + 1) * 4) = *(uint32_t*)&h1;
}

// ---------------- prep x: fp32 -> fp16 permuted ----------------
__global__ void prep_x_kernel(const float* __restrict__ x) {
    size_t n4 = (size_t)MDIM * KDIM / 4;
    size_t stride = (size_t)gridDim.x * blockDim.x;
    const float4* in = (const float4*)x;
    for (size_t i = blockIdx.x * (size_t)blockDim.x + threadIdx.x; i < n4; i += stride) {
        float4 v = in[i];
        cvt_store4(g_xh, i >> 10, ((int)i & 1023) * 4, v);
    }
}

// ---------------- prep w: fold LoRA, fp32 -> fp16 permuted ----------------
__global__ void prep_w_kernel(const float* __restrict__ w, const float* __restrict__ lA,
                              const float* __restrict__ lB) {
    int o = blockIdx.x, tid = threadIdx.x;
    float bv[16];
#pragma unroll
    for (int r = 0; r < 16; r++) bv[r] = lB[o * 16 + r] * 2.0f;
    const float4* wr = (const float4*)(w + (size_t)o * KDIM);
#pragma unroll 4
    for (int i = 0; i < 4; i++) {
        int j = tid + 256 * i;
        float4 acc = wr[j];
#pragma unroll
        for (int r = 0; r < 16; r++) {
            float4 a = ((const float4*)(lA + (size_t)r * KDIM))[j];
            acc.x += bv[r] * a.x; acc.y += bv[r] * a.y;
            acc.z += bv[r] * a.z; acc.w += bv[r] * a.w;
        }
        cvt_store4(g_wh, o, j * 4, acc);
    }
}

// ------- main GEMM: fp16 m16n8k16, BM=128 BN=256 BK=32, 16 warps (4/SMSP) -------
__global__ __launch_bounds__(NTHR, 1)
void lora_gemm_kernel(const float* __restrict__ bias, float* __restrict__ out) {
    extern __shared__ char smem[];
    const int tid = threadIdx.x;
    const int wid = tid >> 5, lane = tid & 31;
    const int wm = wid >> 2, wn = wid & 3;            // 4 x 4 warps, tile 32x64
    const int m0 = blockIdx.x * BM, n0 = blockIdx.y * BN;
    const uint32_t sbase = smem_u32(smem);

    auto issue = [&](int s, int kt) {
        uint32_t st = sbase + s * STAGE_BYTES;
        {                                              // A: 512 chunks of 16B
            int c = tid;
            int row = c >> 2, q = c & 3;
            cp_async16(st + c * 16,
                       (const char*)g_xh + (size_t)(m0 + row) * (KDIM * 2) + kt * 64 + q * 16);
        }
#pragma unroll
        for (int i = 0; i < 2; i++) {                  // B: 1024 chunks
            int c = tid + i * 512;
            int row = c >> 2, q = c & 3;
            cp_async16(st + A_BYTES + c * 16,
                       (const char*)g_wh + (size_t)(n0 + row) * (KDIM * 2) + kt * 64 + q * 16);
        }
    };

    float acc[2][8][4];
#pragma unroll
    for (int ma = 0; ma < 2; ma++)
#pragma unroll
        for (int na = 0; na < 8; na++)
#pragma unroll
            for (int j = 0; j < 4; j++) acc[ma][na][j] = 0.0f;

    issue(0, 0); CP_COMMIT();
    issue(1, 1); CP_COMMIT();

    const int g = lane >> 2, t = lane & 3;
    for (int kt = 0; kt < NKT; ++kt) {
        int s = kt - (kt / 3) * 3;
        if (kt + 2 < NKT) { CP_WAIT1(); } else { CP_WAIT0(); }
        __syncthreads();
        if (kt + 2 < NKT) {
            int s2 = (kt + 2) - ((kt + 2) / 3) * 3;
            issue(s2, kt + 2);
            CP_COMMIT();
        }

        uint32_t aB = sbase + s * STAGE_BYTES;
        uint32_t bB = aB + A_BYTES;
        uint32_t pa = aB + (wm * 32 + g) * 64 + t * 16;
        uint32_t pb = bB + (wn * 64 + g) * 64 + t * 16;

        uint4 u[2], v[2], w[8];
#pragma unroll
        for (int ma = 0; ma < 2; ma++) {
            u[ma] = lds128(pa + ma * (16 * 64));           // row g + 16ma
            v[ma] = lds128(pa + ma * (16 * 64) + 8 * 64);  // row g+8 + 16ma
        }
#pragma unroll
        for (int na = 0; na < 8; na++)
            w[na] = lds128(pb + na * (8 * 64));            // n-row g + 8na

        // k-group 0 (k 0..15)
#pragma unroll
        for (int ma = 0; ma < 2; ma++)
#pragma unroll
            for (int na = 0; na < 8; na++)
                hmma(acc[ma][na], u[ma].x, v[ma].x, u[ma].y, v[ma].y,
                     w[na].x, w[na].y);
        // k-group 1 (k 16..31)
#pragma unroll
        for (int ma = 0; ma < 2; ma++)
#pragma unroll
            for (int na = 0; na < 8; na++)
                hmma(acc[ma][na], u[ma].z, v[ma].z, u[ma].w, v[ma].w,
                     w[na].z, w[na].w);
    }

    // epilogue: fused bias + coalesced float2 stores
    const int r0 = m0 + wm * 32 + g;
    const int cbase = n0 + wn * 64 + t * 2;
    float2 bv[8];
#pragma unroll
    for (int na = 0; na < 8; na++)
        bv[na] = *(const float2*)(bias + cbase + na * 8);
#pragma unroll
    for (int ma = 0; ma < 2; ma++) {
        size_t row = (size_t)(r0 + ma * 16);
#pragma unroll
        for (int na = 0; na < 8; na++) {
            float2 v0 = make_float2(acc[ma][na][0] + bv[na].x, acc[ma][na][1] + bv[na].y);
            float2 v1 = make_float2(acc[ma][na][2] + bv[na].x, acc[ma][na][3] + bv[na].y);
            *(float2*)(out + row * NDIM + cbase + na * 8) = v0;
            *(float2*)(out + (row + 8) * NDIM + cbase + na * 8) = v1;
        }
    }
}

// ---------------- launch ----------------
extern "C" void kernel_launch(void* const* d_in, const int* in_sizes, int n_in,
                              void* d_out, int out_size) {
    const float* x      = (const float*)d_in[0];
    const float* weight = (const float*)d_in[1];
    const float* bias   = (const float*)d_in[2];
    const float* lora_A = (const float*)d_in[3];
    const float* lora_B = (const float*)d_in[4];
    float* out = (float*)d_out;

    cudaFuncSetAttribute(lora_gemm_kernel, cudaFuncAttributeMaxDynamicSharedMemorySize,
                         SMEM_BYTES);

    prep_x_kernel<<<8192, 256>>>(x);
    prep_w_kernel<<<NDIM, 256>>>(weight, lora_A, lora_B);
    dim3 grid(MDIM / BM, NDIM / BN);
    lora_gemm_kernel<<<grid, NTHR, SMEM_BYTES>>>(bias, out);
}